// round 16
// baseline (speedup 1.0000x reference)
#include <cuda_runtime.h>
#include <cuda_fp16.h>
#include <cstdint>

#define NB 8192
#define FD 4096
#define NH 16
#define HI 256
#define HO 1024
#define MD 16384

// Scratch (device globals — no allocation in kernel_launch)
__device__ __half g_w1[NH * HI * HO];               // 8 MB  [h][k=HI][n=HO]
__device__ __half g_w2[NH * HO * HI];               // 8 MB  [h][k'=HO perm'd][n=HI]
__device__ __half g_h[(long long)NB * MD];          // 256 MB (columns perm'd)

// Fast gelu: tanh-form with MUFU tanh.approx.
__device__ __forceinline__ float gelu_f(float v) {
    float u = v * v;
    float inner = v * fmaf(0.0356774081f, u, 0.7978845608f);
    float th;
    asm("tanh.approx.f32 %0, %1;" : "=f"(th) : "f"(inner));
    float hv = 0.5f * v;
    return fmaf(hv, th, hv);
}

__device__ __forceinline__ void ldsm4(unsigned &r0, unsigned &r1, unsigned &r2, unsigned &r3, unsigned addr) {
    asm volatile("ldmatrix.sync.aligned.m8n8.x4.shared.b16 {%0,%1,%2,%3},[%4];"
                 : "=r"(r0), "=r"(r1), "=r"(r2), "=r"(r3) : "r"(addr));
}
__device__ __forceinline__ void ldsm4t(unsigned &r0, unsigned &r1, unsigned &r2, unsigned &r3, unsigned addr) {
    asm volatile("ldmatrix.sync.aligned.m8n8.x4.trans.shared.b16 {%0,%1,%2,%3},[%4];"
                 : "=r"(r0), "=r"(r1), "=r"(r2), "=r"(r3) : "r"(addr));
}
__device__ __forceinline__ void mma16816(float c[4], const unsigned a[4], const unsigned b[2]) {
    asm volatile("mma.sync.aligned.m16n8k16.row.col.f32.f16.f16.f32 "
                 "{%0,%1,%2,%3},{%4,%5,%6,%7},{%8,%9},{%0,%1,%2,%3};"
                 : "+f"(c[0]), "+f"(c[1]), "+f"(c[2]), "+f"(c[3])
                 : "r"(a[0]), "r"(a[1]), "r"(a[2]), "r"(a[3]), "r"(b[0]), "r"(b[1]));
}
#define CP16(s, g) asm volatile("cp.async.cg.shared.global [%0], [%1], 16;\n" :: "r"(s), "l"(g))

// ---------------------------------------------------------------------------
// Prep: W1 flat convert; W2 convert with k-row permutation matching g_h's
// column layout: within each 64-row group, k = ni*8 + tt*2 + bit  ->
// k' = tt*16 + ni*2 + bit   (ni in 0..7, tt in 0..3, bit in 0..1).
// ---------------------------------------------------------------------------
__global__ void __launch_bounds__(256) k_prep_w1(const float* __restrict__ wu) {
    int i = blockIdx.x * 256 + threadIdx.x;
    const int N4 = NH * HI * HO / 4;
    if (i >= N4) return;
    float4 a = *(const float4*)(wu + (long long)i * 4);
    __half2* d = (__half2*)(g_w1 + (long long)i * 4);
    d[0] = __floats2half2_rn(a.x, a.y);
    d[1] = __floats2half2_rn(a.z, a.w);
}

__global__ void __launch_bounds__(256) k_prep_w2(const float* __restrict__ wd) {
    int i = blockIdx.x * 256 + threadIdx.x;          // float4 index
    const int N4 = NH * HO * HI / 4;
    if (i >= N4) return;
    int row = i >> 6;            // h*1024 + k   (64 float4 per 256-wide row)
    int cf4 = i & 63;
    int k = row & 1023;
    int w = k & 63;
    int ni = w >> 3, tt = (w & 7) >> 1, bit = w & 1;
    int kp = (k & ~63) | (tt * 16 + ni * 2 + bit);
    int drow = (row & ~1023) | kp;
    float4 a = *(const float4*)(wd + (long long)i * 4);
    __half2* d = (__half2*)(g_w2 + (long long)drow * HI + cf4 * 4);
    d[0] = __floats2half2_rn(a.x, a.y);
    d[1] = __floats2half2_rn(a.z, a.w);
}

// ---------------------------------------------------------------------------
// k_up_ares: GEMM1, A-resident. Inline x gather+convert (prep_x deleted).
// Epilogue stores to g_h in the column-permuted layout via STG.128.
// ---------------------------------------------------------------------------
__global__ void __launch_bounds__(256, 2) k_up_ares(const float* __restrict__ x,
                                                    const int* __restrict__ perm,
                                                    const float* __restrict__ bias) {
    extern __shared__ char smem[];
    constexpr int BSTG = 64 * 256;         // 16 KB per W1 stage
    const unsigned sAb = (unsigned)__cvta_generic_to_shared(smem);   // 64 KB A
    const unsigned sBb = sAb + 65536u;                               // 3 x 16 KB B

    const int h  = blockIdx.x;
    const int r0 = blockIdx.y << 7;
    const int tid = threadIdx.x;
    const int lane = tid & 31, warp = tid >> 5;
    const int wm = warp & 3, wn = warp >> 2;

    const __half* W1g = g_w1 + (long long)h * HI * HO;

    auto loadB = [&](int st, int s) {
        const __half* Bk = W1g + (long long)((s & 3) * 64) * HO + (s >> 2) * 128;
        const unsigned sb = sBb + (unsigned)st * BSTG;
#pragma unroll
        for (int i = 0; i < 4; i++) {
            int c = tid + i * 256;
            int k = c >> 4, cn = c & 15;
            CP16(sb + k * 256 + ((cn ^ ((k & 7) << 1)) << 4),
                 Bk + (long long)k * HO + cn * 8);
        }
        asm volatile("cp.async.commit_group;\n");
    };

    loadB(0, 0);
    loadB(1, 1);

    // ---- A gather (once): x fp32 -> permuted fp16, direct to swizzled smem.
    // perm is 64-chunk structured: 8-half granules are contiguous in x.
    {
        const int* pm = perm + h * HI;
#pragma unroll
        for (int i = 0; i < 16; i++) {
            int c = tid + i * 256;
            int m = c >> 5, gk = c & 31;
            int p = __ldg(pm + gk * 8);
            const float4* src = (const float4*)(x + (long long)(r0 + m) * FD + p);
            float4 a = src[0], b = src[1];
            uint4 v;
            __half2 t0 = __floats2half2_rn(a.x, a.y); v.x = *(unsigned*)&t0;
            __half2 t1 = __floats2half2_rn(a.z, a.w); v.y = *(unsigned*)&t1;
            __half2 t2 = __floats2half2_rn(b.x, b.y); v.z = *(unsigned*)&t2;
            __half2 t3 = __floats2half2_rn(b.z, b.w); v.w = *(unsigned*)&t3;
            *(uint4*)(smem + (gk >> 3) * 16384 + m * 128 + (((gk & 7) ^ (m & 7)) << 4)) = v;
        }
    }

    float acc[2][8][4] = {};
    const int g = lane >> 2, t = lane & 3;

    for (int s = 0; s < 32; s++) {
        if (s + 1 < 32) asm volatile("cp.async.wait_group 1;\n");
        else            asm volatile("cp.async.wait_group 0;\n");
        __syncthreads();
        if (s + 2 < 32) loadB((s + 2) % 3, s + 2);

        const unsigned sa = sAb + (unsigned)(s & 3) * 16384u;
        const unsigned sb = sBb + (unsigned)(s % 3) * BSTG;
#pragma unroll
        for (int ks = 0; ks < 4; ks++) {
            const int k16 = ks * 2 + (lane >> 4);
            unsigned af[2][4];
#pragma unroll
            for (int mi = 0; mi < 2; mi++) {
                int m = wm * 32 + mi * 16 + (lane & 15);
                ldsm4(af[mi][0], af[mi][1], af[mi][2], af[mi][3],
                      sa + m * 128 + ((k16 ^ (m & 7)) << 4));
            }
            unsigned bf[8][2];
#pragma unroll
            for (int nj = 0; nj < 4; nj++) {
                int k = ks * 16 + (lane & 15);
                int cn = wn * 8 + nj * 2 + (lane >> 4);
                unsigned t0, t1, t2, t3;
                ldsm4t(t0, t1, t2, t3, sb + k * 256 + ((cn ^ ((k & 7) << 1)) << 4));
                bf[nj * 2][0] = t0; bf[nj * 2][1] = t1;
                bf[nj * 2 + 1][0] = t2; bf[nj * 2 + 1][1] = t3;
            }
#pragma unroll
            for (int mi = 0; mi < 2; mi++)
#pragma unroll
                for (int ni = 0; ni < 8; ni++)
                    mma16816(acc[mi][ni], af[mi], bf[ni]);
        }

        if ((s & 3) == 3) {
            // Epilogue for n-chunk s>>2. Store layout: within each 64-col
            // group, this thread's 16 values per row are CONTIGUOUS at
            // col t*16 (new col = t*16 + ni*2 + bit), so 2x STG.128 per row.
            const int cb = h * HO + (s >> 2) * 128;            // bias base (orig cols)
            const int cs = cb + wn * 64 + t * 16;              // store base (perm cols)
#pragma unroll
            for (int mi = 0; mi < 2; mi++) {
                int r = r0 + wm * 32 + mi * 16 + g;
                unsigned pa[8], pb[8];
#pragma unroll
                for (int ni = 0; ni < 8; ni++) {
                    int c = cb + wn * 64 + ni * 8 + t * 2;
                    float b0 = __ldg(bias + c), b1 = __ldg(bias + c + 1);
                    __half2 ha = __floats2half2_rn(gelu_f(acc[mi][ni][0] + b0),
                                                   gelu_f(acc[mi][ni][1] + b1));
                    __half2 hb = __floats2half2_rn(gelu_f(acc[mi][ni][2] + b0),
                                                   gelu_f(acc[mi][ni][3] + b1));
                    pa[ni] = *(unsigned*)&ha;
                    pb[ni] = *(unsigned*)&hb;
                    acc[mi][ni][0] = acc[mi][ni][1] = acc[mi][ni][2] = acc[mi][ni][3] = 0.f;
                }
                uint4* d0 = (uint4*)(g_h + (long long)r * MD + cs);
                d0[0] = make_uint4(pa[0], pa[1], pa[2], pa[3]);
                d0[1] = make_uint4(pa[4], pa[5], pa[6], pa[7]);
                uint4* d1 = (uint4*)(g_h + (long long)(r + 8) * MD + cs);
                d1[0] = make_uint4(pb[0], pb[1], pb[2], pb[3]);
                d1[1] = make_uint4(pb[4], pb[5], pb[6], pb[7]);
            }
        }
    }
}

// ---------------------------------------------------------------------------
// k_down: exact golden kernel (187 us). Reads g_h (perm'd cols) vs g_w2
// (perm'd k-rows) — permutations match, dot products unchanged.
// ---------------------------------------------------------------------------
__global__ void __launch_bounds__(256, 2) k_down(const float* __restrict__ bias,
                                                 const int* __restrict__ perm,
                                                 float* __restrict__ out) {
    constexpr int KT = 16;
    extern __shared__ char smem[];
    constexpr int ASTG = 128 * 128;
    constexpr int BSTG = 64 * 256;
    const unsigned sAb = (unsigned)__cvta_generic_to_shared(smem);
    const unsigned sBb = sAb + 3 * ASTG;

    const int h  = blockIdx.x >> 1;
    const int nt = blockIdx.x & 1;
    const int r0 = blockIdx.y << 7;
    const int n0 = nt << 7;
    const int tid = threadIdx.x;
    const int lane = tid & 31, warp = tid >> 5;
    const int wm = warp & 3, wn = warp >> 2;

    const __half* Ag = g_h + (long long)r0 * MD + h * HO;
    const __half* Bg = g_w2 + (long long)h * HO * HI + n0;

    auto load_stage = [&](int stage, int kt) {
        const unsigned sa = sAb + stage * ASTG;
        const unsigned sb = sBb + stage * BSTG;
        const __half* Agk = Ag + kt * 64;
        const __half* Bgk = Bg + (long long)kt * 64 * HI;
#pragma unroll
        for (int i = 0; i < 4; i++) {
            int c = tid + i * 256;
            int m = c >> 3, g = c & 7;
            CP16(sa + m * 128 + ((g ^ (m & 7)) << 4), Agk + (long long)m * MD + g * 8);
        }
#pragma unroll
        for (int i = 0; i < 4; i++) {
            int c = tid + i * 256;
            int k = c >> 4, cn = c & 15;
            CP16(sb + k * 256 + ((cn ^ ((k & 7) << 1)) << 4), Bgk + (long long)k * HI + cn * 8);
        }
        asm volatile("cp.async.commit_group;\n");
    };

    float acc[2][8][4] = {};

    load_stage(0, 0);

    for (int kt = 0; kt < KT; kt++) {
        if (kt + 1 < KT) {
            load_stage((kt + 1) % 3, kt + 1);
            asm volatile("cp.async.wait_group 1;\n");
        } else {
            asm volatile("cp.async.wait_group 0;\n");
        }
        __syncthreads();
        const int stg = kt % 3;
        const unsigned sa = sAb + stg * ASTG;
        const unsigned sb = sBb + stg * BSTG;
#pragma unroll
        for (int ks = 0; ks < 4; ks++) {
            const int k16 = ks * 2 + (lane >> 4);
            unsigned af[2][4];
#pragma unroll
            for (int mi = 0; mi < 2; mi++) {
                int m = wm * 32 + mi * 16 + (lane & 15);
                ldsm4(af[mi][0], af[mi][1], af[mi][2], af[mi][3],
                      sa + m * 128 + ((k16 ^ (m & 7)) << 4));
            }
            unsigned bf[8][2];
#pragma unroll
            for (int nj = 0; nj < 4; nj++) {
                int k = ks * 16 + (lane & 15);
                int cn = wn * 8 + nj * 2 + (lane >> 4);
                unsigned t0, t1, t2, t3;
                ldsm4t(t0, t1, t2, t3, sb + k * 256 + ((cn ^ ((k & 7) << 1)) << 4));
                bf[nj * 2][0] = t0; bf[nj * 2][1] = t1;
                bf[nj * 2 + 1][0] = t2; bf[nj * 2 + 1][1] = t3;
            }
#pragma unroll
            for (int mi = 0; mi < 2; mi++)
#pragma unroll
                for (int ni = 0; ni < 8; ni++)
                    mma16816(acc[mi][ni], af[mi], bf[ni]);
        }
    }

    const int g = lane >> 2, t = lane & 3;
    const int cb = h * HI + n0;
#pragma unroll
    for (int mi = 0; mi < 2; mi++) {
#pragma unroll
        for (int ni = 0; ni < 8; ni++) {
            int r = r0 + wm * 32 + mi * 16 + g;
            int c = cb + wn * 64 + ni * 8 + t * 2;
            float b0 = __ldg(bias + c), b1 = __ldg(bias + c + 1);
            int p = __ldg(perm + c);   // c even; 64-chunk perm => perm[c+1]=perm[c]+1
            float2 o0; o0.x = acc[mi][ni][0] + b0; o0.y = acc[mi][ni][1] + b1;
            *(float2*)(out + (long long)r * FD + p) = o0;
            float2 o1; o1.x = acc[mi][ni][2] + b0; o1.y = acc[mi][ni][3] + b1;
            *(float2*)(out + (long long)(r + 8) * FD + p) = o1;
        }
    }
}

extern "C" void kernel_launch(void* const* d_in, const int* in_sizes, int n_in,
                              void* d_out, int out_size) {
    const float* x      = (const float*)d_in[0];
    const int*   perm   = (const int*)d_in[1];
    const float* w_up   = (const float*)d_in[2];
    const float* b_up   = (const float*)d_in[3];
    const float* w_down = (const float*)d_in[4];
    const float* b_down = (const float*)d_in[5];
    float* out = (float*)d_out;

    k_prep_w1<<<(NH * HI * HO / 4 + 255) / 256, 256>>>(w_up);
    k_prep_w2<<<(NH * HO * HI / 4 + 255) / 256, 256>>>(w_down);

    constexpr int SMEM_UP = 65536 + 3 * (64 * 256);      // 114688
    constexpr int SMEM_DN = 3 * (128 * 128 + 64 * 256);  // 98304
    cudaFuncSetAttribute(k_up_ares, cudaFuncAttributeMaxDynamicSharedMemorySize, SMEM_UP);
    cudaFuncSetAttribute(k_down,   cudaFuncAttributeMaxDynamicSharedMemorySize, SMEM_DN);

    dim3 g1(NH, NB / 128);       // (16, 64): A-resident, inline gather
    k_up_ares<<<g1, 256, SMEM_UP>>>(x, perm, b_up);

    dim3 g2(NH * 2, NB / 128);   // (32, 64)
    k_down<<<g2, 256, SMEM_DN>>>(b_down, perm, out);
}

// round 17
// speedup vs baseline: 1.4687x; 1.4687x over previous
#include <cuda_runtime.h>
#include <cuda_fp16.h>
#include <cstdint>

#define NB 8192
#define FD 4096
#define NH 16
#define HI 256
#define HO 1024
#define MD 16384

// Scratch (device globals — no allocation in kernel_launch)
__device__ __half g_w1[NH * HI * HO];               // 8 MB  [h][k=HI][n=HO]
__device__ __half g_w2[NH * HO * HI];               // 8 MB  [h][k=HO][n=HI]
__device__ __half g_h[(long long)NB * MD];          // 256 MB

// Fast gelu: tanh-form with MUFU tanh.approx.
__device__ __forceinline__ float gelu_f(float v) {
    float u = v * v;
    float inner = v * fmaf(0.0356774081f, u, 0.7978845608f);
    float th;
    asm("tanh.approx.f32 %0, %1;" : "=f"(th) : "f"(inner));
    float hv = 0.5f * v;
    return fmaf(hv, th, hv);
}

__device__ __forceinline__ void ldsm4(unsigned &r0, unsigned &r1, unsigned &r2, unsigned &r3, unsigned addr) {
    asm volatile("ldmatrix.sync.aligned.m8n8.x4.shared.b16 {%0,%1,%2,%3},[%4];"
                 : "=r"(r0), "=r"(r1), "=r"(r2), "=r"(r3) : "r"(addr));
}
__device__ __forceinline__ void ldsm4t(unsigned &r0, unsigned &r1, unsigned &r2, unsigned &r3, unsigned addr) {
    asm volatile("ldmatrix.sync.aligned.m8n8.x4.trans.shared.b16 {%0,%1,%2,%3},[%4];"
                 : "=r"(r0), "=r"(r1), "=r"(r2), "=r"(r3) : "r"(addr));
}
__device__ __forceinline__ void mma16816(float c[4], const unsigned a[4], const unsigned b[2]) {
    asm volatile("mma.sync.aligned.m16n8k16.row.col.f32.f16.f16.f32 "
                 "{%0,%1,%2,%3},{%4,%5,%6,%7},{%8,%9},{%0,%1,%2,%3};"
                 : "+f"(c[0]), "+f"(c[1]), "+f"(c[2]), "+f"(c[3])
                 : "r"(a[0]), "r"(a[1]), "r"(a[2]), "r"(a[3]), "r"(b[0]), "r"(b[1]));
}
#define CP16(s, g) asm volatile("cp.async.cg.shared.global [%0], [%1], 16;\n" :: "r"(s), "l"(g))

// ---------------------------------------------------------------------------
// Prep: weights fp32 -> fp16 (flat, validated R8..R15 layout)
// ---------------------------------------------------------------------------
__global__ void __launch_bounds__(256) k_prep_w(const float* __restrict__ wu,
                                                const float* __restrict__ wd) {
    int i = blockIdx.x * 256 + threadIdx.x;
    const int N4 = NH * HI * HO / 4;
    if (i >= N4) return;
    float4 a = *(const float4*)(wu + (long long)i * 4);
    __half2* d1 = (__half2*)(g_w1 + (long long)i * 4);
    d1[0] = __floats2half2_rn(a.x, a.y);
    d1[1] = __floats2half2_rn(a.z, a.w);
    float4 b = *(const float4*)(wd + (long long)i * 4);
    __half2* d2 = (__half2*)(g_w2 + (long long)i * 4);
    d2[0] = __floats2half2_rn(b.x, b.y);
    d2[1] = __floats2half2_rn(b.z, b.w);
}

// ---------------------------------------------------------------------------
// k_up_ares: GEMM1, A-resident (R15 mainloop + epilogue, verbatim).
// ONLY change vs R15: the A prologue gathers x directly from the fp32 input
// using perm (64-chunk structured => 8-half granules contiguous), deleting
// the prep_x kernel and its 128 MB DRAM round-trip. Gather block validated
// in R16 (passed correctness).
// ---------------------------------------------------------------------------
__global__ void __launch_bounds__(256, 2) k_up_ares(const float* __restrict__ x,
                                                    const int* __restrict__ perm,
                                                    const float* __restrict__ bias) {
    extern __shared__ char smem[];
    constexpr int BSTG = 64 * 256;         // 16 KB per W1 stage
    const unsigned sAb = (unsigned)__cvta_generic_to_shared(smem);   // 64 KB A
    const unsigned sBb = sAb + 65536u;                               // 3 x 16 KB B

    const int h  = blockIdx.x;
    const int r0 = blockIdx.y << 7;
    const int tid = threadIdx.x;
    const int lane = tid & 31, warp = tid >> 5;
    const int wm = warp & 3, wn = warp >> 2;

    const __half* W1g = g_w1 + (long long)h * HI * HO;

    auto loadB = [&](int st, int s) {
        const __half* Bk = W1g + (long long)((s & 3) * 64) * HO + (s >> 2) * 128;
        const unsigned sb = sBb + (unsigned)st * BSTG;
#pragma unroll
        for (int i = 0; i < 4; i++) {
            int c = tid + i * 256;
            int k = c >> 4, cn = c & 15;
            CP16(sb + k * 256 + ((cn ^ ((k & 7) << 1)) << 4),
                 Bk + (long long)k * HO + cn * 8);
        }
        asm volatile("cp.async.commit_group;\n");
    };

    loadB(0, 0);
    loadB(1, 1);

    // ---- A gather (once): x fp32 -> permuted fp16, direct to swizzled smem.
    {
        const int* pm = perm + h * HI;
#pragma unroll
        for (int i = 0; i < 16; i++) {
            int c = tid + i * 256;
            int m = c >> 5, gk = c & 31;
            int p = __ldg(pm + gk * 8);
            const float4* src = (const float4*)(x + (long long)(r0 + m) * FD + p);
            float4 a = src[0], b = src[1];
            uint4 v;
            __half2 t0 = __floats2half2_rn(a.x, a.y); v.x = *(unsigned*)&t0;
            __half2 t1 = __floats2half2_rn(a.z, a.w); v.y = *(unsigned*)&t1;
            __half2 t2 = __floats2half2_rn(b.x, b.y); v.z = *(unsigned*)&t2;
            __half2 t3 = __floats2half2_rn(b.z, b.w); v.w = *(unsigned*)&t3;
            *(uint4*)(smem + (gk >> 3) * 16384 + m * 128 + (((gk & 7) ^ (m & 7)) << 4)) = v;
        }
    }

    float acc[2][8][4] = {};
    const int g = lane >> 2, t = lane & 3;

    for (int s = 0; s < 32; s++) {
        if (s + 1 < 32) asm volatile("cp.async.wait_group 1;\n");
        else            asm volatile("cp.async.wait_group 0;\n");
        __syncthreads();
        if (s + 2 < 32) loadB((s + 2) % 3, s + 2);

        const unsigned sa = sAb + (unsigned)(s & 3) * 16384u;
        const unsigned sb = sBb + (unsigned)(s % 3) * BSTG;
#pragma unroll
        for (int ks = 0; ks < 4; ks++) {
            const int k16 = ks * 2 + (lane >> 4);
            unsigned af[2][4];
#pragma unroll
            for (int mi = 0; mi < 2; mi++) {
                int m = wm * 32 + mi * 16 + (lane & 15);
                ldsm4(af[mi][0], af[mi][1], af[mi][2], af[mi][3],
                      sa + m * 128 + ((k16 ^ (m & 7)) << 4));
            }
            unsigned bf[8][2];
#pragma unroll
            for (int nj = 0; nj < 4; nj++) {
                int k = ks * 16 + (lane & 15);
                int cn = wn * 8 + nj * 2 + (lane >> 4);
                unsigned t0, t1, t2, t3;
                ldsm4t(t0, t1, t2, t3, sb + k * 256 + ((cn ^ ((k & 7) << 1)) << 4));
                bf[nj * 2][0] = t0; bf[nj * 2][1] = t1;
                bf[nj * 2 + 1][0] = t2; bf[nj * 2 + 1][1] = t3;
            }
#pragma unroll
            for (int mi = 0; mi < 2; mi++)
#pragma unroll
                for (int ni = 0; ni < 8; ni++)
                    mma16816(acc[mi][ni], af[mi], bf[ni]);
        }

        if ((s & 3) == 3) {
            const int cb = h * HO + (s >> 2) * 128;
#pragma unroll
            for (int mi = 0; mi < 2; mi++) {
#pragma unroll
                for (int ni = 0; ni < 8; ni++) {
                    int r = r0 + wm * 32 + mi * 16 + g;
                    int c = cb + wn * 64 + ni * 8 + t * 2;
                    float b0 = __ldg(bias + c), b1 = __ldg(bias + c + 1);
                    float v0 = gelu_f(acc[mi][ni][0] + b0);
                    float v1 = gelu_f(acc[mi][ni][1] + b1);
                    *(__half2*)(g_h + (long long)r * MD + c) = __floats2half2_rn(v0, v1);
                    v0 = gelu_f(acc[mi][ni][2] + b0);
                    v1 = gelu_f(acc[mi][ni][3] + b1);
                    *(__half2*)(g_h + (long long)(r + 8) * MD + c) = __floats2half2_rn(v0, v1);
                    acc[mi][ni][0] = acc[mi][ni][1] = acc[mi][ni][2] = acc[mi][ni][3] = 0.f;
                }
            }
        }
    }
}

// ---------------------------------------------------------------------------
// k_down: exact golden kernel (R8/R12/R14/R15; unchanged — clock canary).
// ---------------------------------------------------------------------------
__global__ void __launch_bounds__(256, 2) k_down(const float* __restrict__ bias,
                                                 const int* __restrict__ perm,
                                                 float* __restrict__ out) {
    constexpr int KT = 16;
    extern __shared__ char smem[];
    constexpr int ASTG = 128 * 128;
    constexpr int BSTG = 64 * 256;
    const unsigned sAb = (unsigned)__cvta_generic_to_shared(smem);
    const unsigned sBb = sAb + 3 * ASTG;

    const int h  = blockIdx.x >> 1;
    const int nt = blockIdx.x & 1;
    const int r0 = blockIdx.y << 7;
    const int n0 = nt << 7;
    const int tid = threadIdx.x;
    const int lane = tid & 31, warp = tid >> 5;
    const int wm = warp & 3, wn = warp >> 2;

    const __half* Ag = g_h + (long long)r0 * MD + h * HO;
    const __half* Bg = g_w2 + (long long)h * HO * HI + n0;

    auto load_stage = [&](int stage, int kt) {
        const unsigned sa = sAb + stage * ASTG;
        const unsigned sb = sBb + stage * BSTG;
        const __half* Agk = Ag + kt * 64;
        const __half* Bgk = Bg + (long long)kt * 64 * HI;
#pragma unroll
        for (int i = 0; i < 4; i++) {
            int c = tid + i * 256;
            int m = c >> 3, g = c & 7;
            CP16(sa + m * 128 + ((g ^ (m & 7)) << 4), Agk + (long long)m * MD + g * 8);
        }
#pragma unroll
        for (int i = 0; i < 4; i++) {
            int c = tid + i * 256;
            int k = c >> 4, cn = c & 15;
            CP16(sb + k * 256 + ((cn ^ ((k & 7) << 1)) << 4), Bgk + (long long)k * HI + cn * 8);
        }
        asm volatile("cp.async.commit_group;\n");
    };

    float acc[2][8][4] = {};

    load_stage(0, 0);

    for (int kt = 0; kt < KT; kt++) {
        if (kt + 1 < KT) {
            load_stage((kt + 1) % 3, kt + 1);
            asm volatile("cp.async.wait_group 1;\n");
        } else {
            asm volatile("cp.async.wait_group 0;\n");
        }
        __syncthreads();
        const int stg = kt % 3;
        const unsigned sa = sAb + stg * ASTG;
        const unsigned sb = sBb + stg * BSTG;
#pragma unroll
        for (int ks = 0; ks < 4; ks++) {
            const int k16 = ks * 2 + (lane >> 4);
            unsigned af[2][4];
#pragma unroll
            for (int mi = 0; mi < 2; mi++) {
                int m = wm * 32 + mi * 16 + (lane & 15);
                ldsm4(af[mi][0], af[mi][1], af[mi][2], af[mi][3],
                      sa + m * 128 + ((k16 ^ (m & 7)) << 4));
            }
            unsigned bf[8][2];
#pragma unroll
            for (int nj = 0; nj < 4; nj++) {
                int k = ks * 16 + (lane & 15);
                int cn = wn * 8 + nj * 2 + (lane >> 4);
                unsigned t0, t1, t2, t3;
                ldsm4t(t0, t1, t2, t3, sb + k * 256 + ((cn ^ ((k & 7) << 1)) << 4));
                bf[nj * 2][0] = t0; bf[nj * 2][1] = t1;
                bf[nj * 2 + 1][0] = t2; bf[nj * 2 + 1][1] = t3;
            }
#pragma unroll
            for (int mi = 0; mi < 2; mi++)
#pragma unroll
                for (int ni = 0; ni < 8; ni++)
                    mma16816(acc[mi][ni], af[mi], bf[ni]);
        }
    }

    const int g = lane >> 2, t = lane & 3;
    const int cb = h * HI + n0;
#pragma unroll
    for (int mi = 0; mi < 2; mi++) {
#pragma unroll
        for (int ni = 0; ni < 8; ni++) {
            int r = r0 + wm * 32 + mi * 16 + g;
            int c = cb + wn * 64 + ni * 8 + t * 2;
            float b0 = __ldg(bias + c), b1 = __ldg(bias + c + 1);
            int p = __ldg(perm + c);   // c even; 64-chunk perm => perm[c+1]=perm[c]+1
            float2 o0; o0.x = acc[mi][ni][0] + b0; o0.y = acc[mi][ni][1] + b1;
            *(float2*)(out + (long long)r * FD + p) = o0;
            float2 o1; o1.x = acc[mi][ni][2] + b0; o1.y = acc[mi][ni][3] + b1;
            *(float2*)(out + (long long)(r + 8) * FD + p) = o1;
        }
    }
}

extern "C" void kernel_launch(void* const* d_in, const int* in_sizes, int n_in,
                              void* d_out, int out_size) {
    const float* x      = (const float*)d_in[0];
    const int*   perm   = (const int*)d_in[1];
    const float* w_up   = (const float*)d_in[2];
    const float* b_up   = (const float*)d_in[3];
    const float* w_down = (const float*)d_in[4];
    const float* b_down = (const float*)d_in[5];
    float* out = (float*)d_out;

    k_prep_w<<<(NH * HI * HO / 4 + 255) / 256, 256>>>(w_up, w_down);

    constexpr int SMEM_UP = 65536 + 3 * (64 * 256);      // 114688
    constexpr int SMEM_DN = 3 * (128 * 128 + 64 * 256);  // 98304
    cudaFuncSetAttribute(k_up_ares, cudaFuncAttributeMaxDynamicSharedMemorySize, SMEM_UP);
    cudaFuncSetAttribute(k_down,   cudaFuncAttributeMaxDynamicSharedMemorySize, SMEM_DN);

    dim3 g1(NH, NB / 128);       // (16, 64): A-resident, inline x gather
    k_up_ares<<<g1, 256, SMEM_UP>>>(x, perm, b_up);

    dim3 g2(NH * 2, NB / 128);   // (32, 64)
    k_down<<<g2, 256, SMEM_DN>>>(b_down, perm, out);
}